// round 12
// baseline (speedup 1.0000x reference)
#include <cuda_runtime.h>
#include <cstdint>

typedef unsigned long long ull;

#define BB 512
#define TT 1024
#define IDIM 15
#define HH 64
#define ODIM 11
#define CH 16
#define NCH (TT/CH)

// scratch (static __device__ — no allocations in kernel_launch)
__device__ __align__(16) float g_xpad[(size_t)BB*TT*16];   // x padded 15 -> 16

// ---- f32x2 helpers ----
__device__ __forceinline__ ull ffma2(ull a, ull b, ull c){
    ull d; asm("fma.rn.f32x2 %0, %1, %2, %3;" : "=l"(d) : "l"(a), "l"(b), "l"(c)); return d;
}
__device__ __forceinline__ ull fadd2(ull a, ull b){
    ull d; asm("add.rn.f32x2 %0, %1, %2;" : "=l"(d) : "l"(a), "l"(b)); return d;
}
__device__ __forceinline__ ull pack2(float x, float y){
    ull r; asm("mov.b64 %0, {%1, %2};" : "=l"(r) : "f"(x), "f"(y)); return r;
}
__device__ __forceinline__ float2 unpack2(ull v){
    float2 r; asm("mov.b64 {%0, %1}, %2;" : "=f"(r.x), "=f"(r.y) : "l"(v)); return r;
}
// BSP rendezvous: BOTH warps of a batch execute bar.sync (count 64).
#define BAR64(id) asm volatile("bar.sync %0, 64;" :: "r"(id) : "memory")

// ---- kernel 0: pad x [B,T,15] -> [B,T,16], float4 both directions via smem ----
__global__ void __launch_bounds__(256) pad_x_kernel(const float* __restrict__ x){
    __shared__ float xsm[256*IDIM];
    const int tid = threadIdx.x;
    const float4* src4 = (const float4*)(x + (size_t)blockIdx.x * (256*IDIM));
    #pragma unroll
    for (int k=0;k<4;k++){
        int idx = tid + k*256;
        if (idx < 960) ((float4*)xsm)[idx] = src4[idx];
    }
    __syncthreads();
    float4* dst4 = (float4*)(g_xpad + (size_t)blockIdx.x * (256*16));
    #pragma unroll
    for (int k=0;k<4;k++){
        int idx = tid + k*256;
        int row = idx >> 2, q = idx & 3;
        const float* rp = xsm + row*IDIM + q*4;
        float f0 = rp[0], f1 = rp[1], f2 = rp[2];
        float f3 = (q == 3) ? 0.f : rp[3];
        dst4[idx] = make_float4(f0, f1, f2, f3);
    }
}

// ---- kernel 1: BSP warp-specialized, rnn on HIGH wids ----
// rnn warps = wid 4..7 (hi-wid-first SMSP arbiter priority)
// helper warps = wid 0..3 (xproj producer + decoder)
// Interval c: rnn chunk c (reads xp[c&1], writes ring[c&1]);
//             helper builds xp(c+1) into xp[(c+1)&1], decodes ring[(c-1)&1].
__global__ void __launch_bounds__(256,1) rnn_fused_kernel(
    const float* __restrict__ W_ih, const float* __restrict__ b_ih,
    const float* __restrict__ W_hh, const float* __restrict__ b_hh,
    const float* __restrict__ W_dec, const float* __restrict__ b_dec,
    float* __restrict__ out, float* __restrict__ h_out)
{
    __shared__ __align__(16) float xs[2][4][CH*16];     // raw x chunks        8KB
    __shared__ __align__(16) ull  xp[2][4][CH][32];     // xproj pairs        32KB
    __shared__ __align__(16) ull  ring[4][2][CH][32];   // h history          32KB

    const int tid = threadIdx.x;
    const int wid = tid >> 5;
    const int l   = tid & 31;

    if (wid >= 4){
        // ============ RNN warp (HIGH priority): batch b = blk*4 + (wid-4) ============
        const int p   = wid - 4;
        const int b   = blockIdx.x * 4 + p;
        const int j0  = 2*l, j1 = j0 + 1;
        const int bar = p + 1;

        ull w0[32], w1[32];
        {
            const ull* wp = (const ull*)W_hh;
            #pragma unroll
            for (int q=0;q<32;q++){ w0[q] = wp[j0*32+q]; w1[q] = wp[j1*32+q]; }
        }

        ring[p][1][CH-1][l] = 0ULL;      // h_{-1} (chunk 0 reads ring[1][CH-1])
        ull hlast = 0ULL;

        BAR64(bar);                      // S_0: xp(0) ready
        for (int c=0; c<NCH; c++){
            const ull* xpb   = &xp[c&1][p][0][0];
            ull*       rbuf  = &ring[p][c&1][0][0];
            const ull* hprev = &ring[p][(c&1)^1][CH-1][0];

            #pragma unroll 4
            for (int tt=0; tt<CH; tt++){
                ull xa = xpb[tt*32 + l];                     // LDS.64
                const ulonglong2* hp = (const ulonglong2*)hprev;
                ull aa0=0ULL, aa1=0ULL, ab0=0ULL, ab1=0ULL;
                #pragma unroll
                for (int q=0;q<16;q++){
                    ulonglong2 hv = hp[q];
                    aa0 = ffma2(hv.x, w0[2*q],   aa0);
                    aa1 = ffma2(hv.x, w1[2*q],   aa1);
                    ab0 = ffma2(hv.y, w0[2*q+1], ab0);
                    ab1 = ffma2(hv.y, w1[2*q+1], ab1);
                }
                float2 s0 = unpack2(fadd2(aa0, ab0));
                float2 s1 = unpack2(fadd2(aa1, ab1));
                float2 xv = unpack2(xa);
                float h0v = fmaxf(s0.x + s0.y + xv.x, 0.f);
                float h1v = fmaxf(s1.x + s1.y + xv.y, 0.f);
                ull hpk = pack2(h0v, h1v);
                rbuf[tt*32 + l] = hpk;
                hprev = rbuf + tt*32;
                hlast = hpk;
                asm volatile("" ::: "memory");
            }
            BAR64(bar);                  // S_{c+1}: publish ring[c&1]
        }
        ((ull*)h_out)[b*32 + l] = hlast;

    } else {
        // ============ helper warp (LOW priority): xproj + dec, batch p = wid ============
        const int p   = wid;
        const int b   = blockIdx.x * 4 + p;
        const int j0  = 2*l, j1 = j0 + 1;
        const int bar = p + 1;

        // W_ih rows j0,j1, i-paired (i=15 padded with 0)
        ull wi0[8], wi1[8];
        #pragma unroll
        for (int q=0;q<8;q++){
            float a0 = W_ih[j0*IDIM + 2*q];
            float a1 = (2*q+1 < IDIM) ? W_ih[j0*IDIM + 2*q + 1] : 0.f;
            wi0[q] = pack2(a0,a1);
            float c0 = W_ih[j1*IDIM + 2*q];
            float c1 = (2*q+1 < IDIM) ? W_ih[j1*IDIM + 2*q + 1] : 0.f;
            wi1[q] = pack2(c0,c1);
        }
        const ull bias0 = pack2(b_ih[j0]+b_hh[j0], 0.f);
        const ull bias1 = pack2(b_ih[j1]+b_hh[j1], 0.f);

        // decoder: lane l<22 -> output o=l>>1, K-half = l&1
        const int o = l >> 1;
        const bool half0 = (l & 1) == 0;
        const bool dec_store = (l < 22) && half0;
        const int hoff = half0 ? 0 : 8;   // ulonglong2 offset into h row
        ull wd[16];
        float bdec = 0.f;
        if (l < 22){
            const ull* wdp = (const ull*)W_dec;
            #pragma unroll
            for (int q=0;q<16;q++) wd[q] = wdp[o*32 + (half0?0:16) + q];
            bdec = b_dec[o];
        } else {
            #pragma unroll
            for (int q=0;q<16;q++) wd[q] = 0ULL;
        }

        const uint32_t xs_base = (uint32_t)__cvta_generic_to_shared(&xs[0][p][0]);
        const float* xsrc = g_xpad + (size_t)b * (TT*16);

        auto prefetch = [&](int c){
            if (c < NCH){
                const float* src = xsrc + (size_t)c * (CH*16);
                uint32_t dst = xs_base + (uint32_t)(c & 1) * (uint32_t)sizeof(xs[0]);
                #pragma unroll
                for (int q=0;q<2;q++){
                    int idx = q*32 + l;
                    asm volatile("cp.async.ca.shared.global [%0], [%1], 16;\n"
                        :: "r"(dst + (uint32_t)(idx*16)), "l"(src + idx*4) : "memory");
                }
            }
            asm volatile("cp.async.commit_group;\n" ::: "memory");
        };

        auto compute_xp = [&](int c){    // xproj for chunk c -> xp[c&1][p]
            const float* xb = &xs[c & 1][p][0];
            ull* dst = &xp[c & 1][p][0][0];
            #pragma unroll 4
            for (int tt=0; tt<CH; tt++){
                const ulonglong2* xv = (const ulonglong2*)(xb + tt*16);
                ull xa0 = bias0, xa1 = bias1;
                #pragma unroll
                for (int q=0;q<4;q++){
                    ulonglong2 xq = xv[q];
                    xa0 = ffma2(xq.x, wi0[2*q],   xa0);
                    xa1 = ffma2(xq.x, wi1[2*q],   xa1);
                    xa0 = ffma2(xq.y, wi0[2*q+1], xa0);
                    xa1 = ffma2(xq.y, wi1[2*q+1], xa1);
                }
                float2 s0 = unpack2(xa0), s1 = unpack2(xa1);
                dst[tt*32 + l] = pack2(s0.x + s0.y, s1.x + s1.y);
            }
        };

        auto dec_chunk = [&](int c, float* outp){  // decode ring[c&1] -> out
            const ull* rbuf = &ring[p][c&1][0][0];
            #pragma unroll 4
            for (int s=0; s<CH; s++){
                const ulonglong2* hd = (const ulonglong2*)(rbuf + s*32 + hoff*2);
                ull d0=0ULL, d1=0ULL;
                #pragma unroll
                for (int q=0;q<8;q++){
                    ulonglong2 hv = hd[q];
                    d0 = ffma2(hv.x, wd[2*q],   d0);
                    d1 = ffma2(hv.y, wd[2*q+1], d1);
                }
                float2 ds = unpack2(fadd2(d0,d1));
                float dp = ds.x + ds.y;
                float dq = __shfl_down_sync(0xffffffffu, dp, 1);
                if (dec_store){
                    outp[(size_t)(c*CH + s)*ODIM + o] = fmaxf(dp + dq + bdec, 0.f);
                }
            }
        };

        float* outp = out + (size_t)b * (TT*ODIM);

        // prime: chunks 0,1 in flight; xp(0) built
        prefetch(0);
        prefetch(1);
        asm volatile("cp.async.wait_group 1;\n" ::: "memory");   // chunk 0 landed
        compute_xp(0);
        BAR64(bar);                      // S_0: xp(0) published

        for (int c=0; c<NCH; c++){
            // build xp(c+1) while rnn runs chunk c
            if (c+1 < NCH){
                prefetch(c+2);
                asm volatile("cp.async.wait_group 1;\n" ::: "memory"); // chunk c+1 landed
                compute_xp(c+1);
            }
            // decode previous chunk (ring[(c-1)&1]; rnn is writing ring[c&1])
            if (c > 0) dec_chunk(c-1, outp);
            BAR64(bar);                  // S_{c+1}
        }
        // after final barrier: rnn done; decode last chunk
        dec_chunk(NCH-1, outp);
    }
}

extern "C" void kernel_launch(void* const* d_in, const int* in_sizes, int n_in,
                              void* d_out, int out_size)
{
    const float* x     = (const float*)d_in[0];
    const float* W_ih  = (const float*)d_in[1];
    const float* b_ih  = (const float*)d_in[2];
    const float* W_hh  = (const float*)d_in[3];
    const float* b_hh  = (const float*)d_in[4];
    const float* W_dec = (const float*)d_in[5];
    const float* b_dec = (const float*)d_in[6];
    float* out = (float*)d_out;

    (void)in_sizes; (void)n_in; (void)out_size;

    pad_x_kernel<<<(BB*TT)/256, 256>>>(x);
    rnn_fused_kernel<<<BB/4, 256>>>(W_ih, b_ih, W_hh, b_hh, W_dec, b_dec,
                                    out, out + (size_t)BB*TT*ODIM);
}

// round 13
// speedup vs baseline: 1.0875x; 1.0875x over previous
#include <cuda_runtime.h>
#include <cstdint>

typedef unsigned long long ull;

#define BB 512
#define TT 1024
#define IDIM 15
#define HH 64
#define ODIM 11
#define CHUNK 64
#define NCHUNK (TT/CHUNK)

// scratch (static __device__ — no allocations in kernel_launch)
__device__ __align__(16) float g_xpad[(size_t)BB*TT*16];   // x padded 15 -> 16
__device__ __align__(16) float g_hs[(size_t)BB*TT*HH];     // all hidden states

// ---- f32x2 helpers ----
__device__ __forceinline__ ull ffma2(ull a, ull b, ull c){
    ull d; asm("fma.rn.f32x2 %0, %1, %2, %3;" : "=l"(d) : "l"(a), "l"(b), "l"(c)); return d;
}
__device__ __forceinline__ ull fadd2(ull a, ull b){
    ull d; asm("add.rn.f32x2 %0, %1, %2;" : "=l"(d) : "l"(a), "l"(b)); return d;
}
__device__ __forceinline__ ull pack2(float x, float y){
    ull r; asm("mov.b64 %0, {%1, %2};" : "=l"(r) : "f"(x), "f"(y)); return r;
}
__device__ __forceinline__ float2 unpack2(ull v){
    float2 r; asm("mov.b64 {%0, %1}, %2;" : "=f"(r.x), "=f"(r.y) : "l"(v)); return r;
}

// ---- kernel 0: pad x [B,T,15] -> [B,T,16], float4 both directions via smem ----
__global__ void __launch_bounds__(256) pad_x_kernel(const float* __restrict__ x){
    __shared__ float xsm[256*IDIM];
    const int tid = threadIdx.x;
    const float4* src4 = (const float4*)(x + (size_t)blockIdx.x * (256*IDIM));
    #pragma unroll
    for (int k=0;k<4;k++){
        int idx = tid + k*256;
        if (idx < 960) ((float4*)xsm)[idx] = src4[idx];
    }
    __syncthreads();
    float4* dst4 = (float4*)(g_xpad + (size_t)blockIdx.x * (256*16));
    #pragma unroll
    for (int k=0;k<4;k++){
        int idx = tid + k*256;
        int row = idx >> 2, q = idx & 3;
        const float* rp = xsm + row*IDIM + q*4;
        float f0 = rp[0], f1 = rp[1], f2 = rp[2];
        float f3 = (q == 3) ? 0.f : rp[3];
        dst4[idx] = make_float4(f0, f1, f2, f3);
    }
}

// ---- kernel 1: fused input-proj + recurrence. warp == one batch row ----
__global__ void __launch_bounds__(128,1) rnn_kernel(
    const float* __restrict__ W_ih, const float* __restrict__ b_ih,
    const float* __restrict__ W_hh, const float* __restrict__ b_hh,
    float* __restrict__ h_out)
{
    __shared__ __align__(16) float xs[2][4][CHUNK*16];   // double-buffered x chunks
    __shared__ __align__(16) ull  h_sh[4][2][32];        // per-warp double-buffered h

    const int wid = threadIdx.x >> 5;
    const int l   = threadIdx.x & 31;
    const int b   = blockIdx.x * 4 + wid;
    const int j0 = 2*l, j1 = 2*l + 1;

    // W_hh rows j0,j1 in registers, k-paired as f32x2
    ull w0[32], w1[32];
    {
        const ull* wp = (const ull*)W_hh;
        #pragma unroll
        for (int q=0;q<32;q++){ w0[q] = wp[j0*32+q]; w1[q] = wp[j1*32+q]; }
    }
    // W_ih rows, i-paired, padded i=15 with 0
    ull wi0[8], wi1[8];
    #pragma unroll
    for (int q=0;q<8;q++){
        float a0 = W_ih[j0*IDIM + 2*q];
        float a1 = (2*q+1 < IDIM) ? W_ih[j0*IDIM + 2*q + 1] : 0.f;
        wi0[q] = pack2(a0,a1);
        float c0 = W_ih[j1*IDIM + 2*q];
        float c1 = (2*q+1 < IDIM) ? W_ih[j1*IDIM + 2*q + 1] : 0.f;
        wi1[q] = pack2(c0,c1);
    }
    const ull bias0 = pack2(b_ih[j0]+b_hh[j0], 0.f);
    const ull bias1 = pack2(b_ih[j1]+b_hh[j1], 0.f);

    h_sh[wid][1][l] = 0ULL;   // h_{-1} = 0 (t=0 reads slot 1)

    const uint32_t xs_base0 = (uint32_t)__cvta_generic_to_shared(&xs[0][wid][0]);
    const size_t xrow = (size_t)b * (TT*16);

    auto prefetch = [&](int c){
        if (c < NCHUNK){
            const float* src = g_xpad + xrow + (size_t)c*(CHUNK*16);
            uint32_t dst = xs_base0 + (uint32_t)(c & 1) * (uint32_t)sizeof(xs[0]);
            #pragma unroll
            for (int q=0;q<8;q++){
                asm volatile("cp.async.ca.shared.global [%0], [%1], 16;\n"
                    :: "r"(dst + (uint32_t)((q*32+l)*16)), "l"(src + (q*32+l)*4) : "memory");
            }
        }
        asm volatile("cp.async.commit_group;\n" ::: "memory");
    };

    prefetch(0);

    ull* hs_ptr = ((ull*)g_hs) + (size_t)b * (TT*32) + l;
    ull hlast = 0ULL;

    for (int c=0; c<NCHUNK; c++){
        prefetch(c+1);                                        // overlap next chunk
        asm volatile("cp.async.wait_group 1;\n" ::: "memory");// chunk c landed
        __syncwarp();
        const float* xbuf = &xs[c & 1][wid][0];

        #pragma unroll 4
        for (int tt=0; tt<CHUNK; tt++){
            const int rs = (tt & 1) ^ 1;   // read  h_{t-1}
            const int ws =  tt & 1;        // write h_t
            // input projection FIRST (independent of h -> fills STS->LDS shadow).
            // ax0/ax1 are per-output accumulators; their halves are h-summed at
            // the end, so they can directly SEED the recurrence chains below.
            const ulonglong2* xv = (const ulonglong2*)(xbuf + tt*16);
            ull ax0 = bias0, ax1 = bias1;
            #pragma unroll
            for (int q=0;q<4;q++){
                ulonglong2 xq = xv[q];
                ax0 = ffma2(xq.x, wi0[2*q],   ax0);
                ax1 = ffma2(xq.x, wi1[2*q],   ax1);
                ax0 = ffma2(xq.y, wi0[2*q+1], ax0);
                ax1 = ffma2(xq.y, wi1[2*q+1], ax1);
            }
            // recurrence: chains seeded with the xproj accumulators (one fewer
            // dependent fadd2 in the tail; hsum keeps the math identical).
            const ulonglong2* hp = (const ulonglong2*)&h_sh[wid][rs][0];
            ull aa0=ax0, aa1=ax1, ab0=0ULL, ab1=0ULL;
            #pragma unroll
            for (int q=0;q<16;q++){
                ulonglong2 hv = hp[q];
                aa0 = ffma2(hv.x, w0[2*q],   aa0);
                aa1 = ffma2(hv.x, w1[2*q],   aa1);
                ab0 = ffma2(hv.y, w0[2*q+1], ab0);
                ab1 = ffma2(hv.y, w1[2*q+1], ab1);
            }
            float2 s0 = unpack2(fadd2(aa0, ab0));
            float2 s1 = unpack2(fadd2(aa1, ab1));
            float h0v = fmaxf(s0.x + s0.y, 0.f);
            float h1v = fmaxf(s1.x + s1.y, 0.f);
            ull hpk = pack2(h0v, h1v);
            h_sh[wid][ws][l] = hpk;    // exchange for next step
            *hs_ptr = hpk;             // coalesced STG.64 of h_t for decoder kernel
            hs_ptr += 32;
            hlast = hpk;
            // converged warp: compiler-only ordering between STS and next LDS
            asm volatile("" ::: "memory");
        }
    }
    // final hidden state -> tail of d_out ( [1,B,H] )
    ((ull*)h_out)[b*32 + l] = hlast;
}

// ---- kernel 2: decoder out = relu(hs @ W_dec^T + b_dec), hs rows staged via smem ----
__global__ void __launch_bounds__(128) dec_kernel(
    const float* __restrict__ W_dec, const float* __restrict__ b_dec,
    float* __restrict__ out)
{
    __shared__ __align__(16) float wd_f[ODIM*HH];
    __shared__ float bd[ODIM];
    __shared__ __align__(16) ull  rows[4][32*33];       // padded stride: 2-way max conflict
    __shared__ __align__(16) float outsh[4][32*ODIM];

    for (int i = threadIdx.x; i < ODIM*HH; i += 128) wd_f[i] = W_dec[i];
    if (threadIdx.x < ODIM) bd[threadIdx.x] = b_dec[threadIdx.x];
    __syncthreads();

    const int wid = threadIdx.x >> 5;
    const int l   = threadIdx.x & 31;
    const int ngroups = (BB*TT)/32;   // 16384 groups of 32 rows

    for (int g = blockIdx.x*4 + wid; g < ngroups; g += gridDim.x*4){
        // coalesced load of 32 rows x 64 floats into padded smem
        const ulonglong2* src = (const ulonglong2*)(g_hs + (size_t)g * (32*64));
        #pragma unroll
        for (int q=0;q<16;q++){
            int idx = q*32 + l;            // 0..511 (16B units)
            ulonglong2 v = src[idx];
            int row = idx >> 4;
            int cu  = (idx & 15) * 2;
            rows[wid][row*33 + cu]     = v.x;
            rows[wid][row*33 + cu + 1] = v.y;
        }
        __syncwarp();
        const ull* hr  = &rows[wid][l*33];
        const ull* wd2 = (const ull*)wd_f;
        #pragma unroll
        for (int o=0;o<ODIM;o++){
            ull a0=0ULL, a1=0ULL;
            #pragma unroll
            for (int kk=0;kk<32;kk+=2){
                a0 = ffma2(hr[kk],   wd2[o*32+kk],   a0);
                a1 = ffma2(hr[kk+1], wd2[o*32+kk+1], a1);
            }
            float2 s = unpack2(fadd2(a0,a1));
            outsh[wid][l*ODIM + o] = fmaxf(s.x + s.y + bd[o], 0.f);
        }
        __syncwarp();
        // coalesced store: 32*11 = 352 floats = 88 float4
        float4* dst = (float4*)(out + (size_t)g * (32*ODIM));
        const float4* osrc = (const float4*)&outsh[wid][0];
        #pragma unroll
        for (int q=0;q<3;q++){
            int idx = q*32 + l;
            if (idx < 88) dst[idx] = osrc[idx];
        }
        __syncwarp();
    }
}

extern "C" void kernel_launch(void* const* d_in, const int* in_sizes, int n_in,
                              void* d_out, int out_size)
{
    const float* x     = (const float*)d_in[0];
    const float* W_ih  = (const float*)d_in[1];
    const float* b_ih  = (const float*)d_in[2];
    const float* W_hh  = (const float*)d_in[3];
    const float* b_hh  = (const float*)d_in[4];
    const float* W_dec = (const float*)d_in[5];
    const float* b_dec = (const float*)d_in[6];
    float* out = (float*)d_out;

    (void)in_sizes; (void)n_in; (void)out_size;

    pad_x_kernel<<<(BB*TT)/256, 256>>>(x);
    rnn_kernel<<<BB/4, 128>>>(W_ih, b_ih, W_hh, b_hh, out + (size_t)BB*TT*ODIM);
    dec_kernel<<<1024, 128>>>(W_dec, b_dec, out);
}

// round 14
// speedup vs baseline: 1.1042x; 1.0154x over previous
#include <cuda_runtime.h>
#include <cuda_fp16.h>
#include <cstdint>

typedef unsigned long long ull;

#define BB 512
#define TT 1024
#define IDIM 15
#define HH 64
#define ODIM 11
#define CHUNK 64
#define NCHUNK (TT/CHUNK)

// scratch (static __device__ — no allocations in kernel_launch)
__device__ __align__(16) float   g_xpad[(size_t)BB*TT*16];   // x padded 15 -> 16
__device__ __align__(16) __half2 g_hs[(size_t)BB*TT*32];     // hidden states, fp16 pairs

// ---- f32x2 helpers ----
__device__ __forceinline__ ull ffma2(ull a, ull b, ull c){
    ull d; asm("fma.rn.f32x2 %0, %1, %2, %3;" : "=l"(d) : "l"(a), "l"(b), "l"(c)); return d;
}
__device__ __forceinline__ ull fadd2(ull a, ull b){
    ull d; asm("add.rn.f32x2 %0, %1, %2;" : "=l"(d) : "l"(a), "l"(b)); return d;
}
__device__ __forceinline__ ull pack2(float x, float y){
    ull r; asm("mov.b64 %0, {%1, %2};" : "=l"(r) : "f"(x), "f"(y)); return r;
}
__device__ __forceinline__ float2 unpack2(ull v){
    float2 r; asm("mov.b64 {%0, %1}, %2;" : "=f"(r.x), "=f"(r.y) : "l"(v)); return r;
}

// ---- kernel 0: pad x [B,T,15] -> [B,T,16], float4 both directions via smem ----
__global__ void __launch_bounds__(256) pad_x_kernel(const float* __restrict__ x){
    __shared__ float xsm[256*IDIM];
    const int tid = threadIdx.x;
    const float4* src4 = (const float4*)(x + (size_t)blockIdx.x * (256*IDIM));
    #pragma unroll
    for (int k=0;k<4;k++){
        int idx = tid + k*256;
        if (idx < 960) ((float4*)xsm)[idx] = src4[idx];
    }
    __syncthreads();
    float4* dst4 = (float4*)(g_xpad + (size_t)blockIdx.x * (256*16));
    #pragma unroll
    for (int k=0;k<4;k++){
        int idx = tid + k*256;
        int row = idx >> 2, q = idx & 3;
        const float* rp = xsm + row*IDIM + q*4;
        float f0 = rp[0], f1 = rp[1], f2 = rp[2];
        float f3 = (q == 3) ? 0.f : rp[3];
        dst4[idx] = make_float4(f0, f1, f2, f3);
    }
}

// ---- kernel 1: fused input-proj + recurrence. warp == one batch row ----
__global__ void __launch_bounds__(128,1) rnn_kernel(
    const float* __restrict__ W_ih, const float* __restrict__ b_ih,
    const float* __restrict__ W_hh, const float* __restrict__ b_hh,
    float* __restrict__ h_out)
{
    __shared__ __align__(16) float xs[2][4][CHUNK*16];   // double-buffered x chunks
    __shared__ __align__(16) ull  h_sh[4][2][32];        // per-warp double-buffered h

    const int wid = threadIdx.x >> 5;
    const int l   = threadIdx.x & 31;
    const int b   = blockIdx.x * 4 + wid;
    const int j0 = 2*l, j1 = 2*l + 1;

    // W_hh rows j0,j1 in registers, k-paired as f32x2
    ull w0[32], w1[32];
    {
        const ull* wp = (const ull*)W_hh;
        #pragma unroll
        for (int q=0;q<32;q++){ w0[q] = wp[j0*32+q]; w1[q] = wp[j1*32+q]; }
    }
    // W_ih rows, i-paired, padded i=15 with 0
    ull wi0[8], wi1[8];
    #pragma unroll
    for (int q=0;q<8;q++){
        float a0 = W_ih[j0*IDIM + 2*q];
        float a1 = (2*q+1 < IDIM) ? W_ih[j0*IDIM + 2*q + 1] : 0.f;
        wi0[q] = pack2(a0,a1);
        float c0 = W_ih[j1*IDIM + 2*q];
        float c1 = (2*q+1 < IDIM) ? W_ih[j1*IDIM + 2*q + 1] : 0.f;
        wi1[q] = pack2(c0,c1);
    }
    const ull bias0 = pack2(b_ih[j0]+b_hh[j0], 0.f);
    const ull bias1 = pack2(b_ih[j1]+b_hh[j1], 0.f);

    h_sh[wid][1][l] = 0ULL;   // h_{-1} = 0 (t=0 reads slot 1)

    const uint32_t xs_base0 = (uint32_t)__cvta_generic_to_shared(&xs[0][wid][0]);
    const size_t xrow = (size_t)b * (TT*16);

    auto prefetch = [&](int c){
        if (c < NCHUNK){
            const float* src = g_xpad + xrow + (size_t)c*(CHUNK*16);
            uint32_t dst = xs_base0 + (uint32_t)(c & 1) * (uint32_t)sizeof(xs[0]);
            #pragma unroll
            for (int q=0;q<8;q++){
                asm volatile("cp.async.ca.shared.global [%0], [%1], 16;\n"
                    :: "r"(dst + (uint32_t)((q*32+l)*16)), "l"(src + (q*32+l)*4) : "memory");
            }
        }
        asm volatile("cp.async.commit_group;\n" ::: "memory");
    };

    prefetch(0);

    __half2* hs_ptr = g_hs + (size_t)b * (TT*32) + l;
    ull hlast = 0ULL;

    for (int c=0; c<NCHUNK; c++){
        prefetch(c+1);                                        // overlap next chunk
        asm volatile("cp.async.wait_group 1;\n" ::: "memory");// chunk c landed
        __syncwarp();
        const float* xbuf = &xs[c & 1][wid][0];

        #pragma unroll 4
        for (int tt=0; tt<CHUNK; tt++){
            const int rs = (tt & 1) ^ 1;   // read  h_{t-1}
            const int ws =  tt & 1;        // write h_t
            // input projection FIRST (independent of h -> fills STS->LDS shadow).
            const ulonglong2* xv = (const ulonglong2*)(xbuf + tt*16);
            ull ax0 = bias0, ax1 = bias1;
            #pragma unroll
            for (int q=0;q<4;q++){
                ulonglong2 xq = xv[q];
                ax0 = ffma2(xq.x, wi0[2*q],   ax0);
                ax1 = ffma2(xq.x, wi1[2*q],   ax1);
                ax0 = ffma2(xq.y, wi0[2*q+1], ax0);
                ax1 = ffma2(xq.y, wi1[2*q+1], ax1);
            }
            // recurrence: chains seeded with xproj accumulators (fp32 throughout)
            const ulonglong2* hp = (const ulonglong2*)&h_sh[wid][rs][0];
            ull aa0=ax0, aa1=ax1, ab0=0ULL, ab1=0ULL;
            #pragma unroll
            for (int q=0;q<16;q++){
                ulonglong2 hv = hp[q];
                aa0 = ffma2(hv.x, w0[2*q],   aa0);
                aa1 = ffma2(hv.x, w1[2*q],   aa1);
                ab0 = ffma2(hv.y, w0[2*q+1], ab0);
                ab1 = ffma2(hv.y, w1[2*q+1], ab1);
            }
            float2 s0 = unpack2(fadd2(aa0, ab0));
            float2 s1 = unpack2(fadd2(aa1, ab1));
            float h0v = fmaxf(s0.x + s0.y, 0.f);
            float h1v = fmaxf(s1.x + s1.y, 0.f);
            ull hpk = pack2(h0v, h1v);
            h_sh[wid][ws][l] = hpk;                    // fp32 exchange for next step
            *hs_ptr = __floats2half2_rn(h0v, h1v);     // fp16 pair for decoder (STG.32)
            hs_ptr += 32;
            hlast = hpk;
            asm volatile("" ::: "memory");
        }
    }
    // final hidden state -> tail of d_out ( [1,B,H] ), full fp32
    ((ull*)h_out)[b*32 + l] = hlast;
}

// ---- kernel 2: decoder out = relu(hs @ W_dec^T + b_dec), fp16 hs -> fp32 math ----
__global__ void __launch_bounds__(128) dec_kernel(
    const float* __restrict__ W_dec, const float* __restrict__ b_dec,
    float* __restrict__ out)
{
    __shared__ __align__(16) float wd_f[ODIM*HH];
    __shared__ float bd[ODIM];
    __shared__ __align__(16) ull  rows[4][32*33];       // fp32 pairs, padded stride
    __shared__ __align__(16) float outsh[4][32*ODIM];

    for (int i = threadIdx.x; i < ODIM*HH; i += 128) wd_f[i] = W_dec[i];
    if (threadIdx.x < ODIM) bd[threadIdx.x] = b_dec[threadIdx.x];
    __syncthreads();

    const int wid = threadIdx.x >> 5;
    const int l   = threadIdx.x & 31;
    const int ngroups = (BB*TT)/32;   // 16384 groups of 32 rows

    for (int g = blockIdx.x*4 + wid; g < ngroups; g += gridDim.x*4){
        // coalesced load of 32 rows x 64 halfs (4KB); convert to fp32 while staging
        const uint4* src = (const uint4*)(g_hs + (size_t)g * (32*32));
        #pragma unroll
        for (int q=0;q<8;q++){
            int idx = q*32 + l;             // 0..255 (16B = 8 halfs each)
            uint4 v = src[idx];
            int row = idx >> 3;             // 8 uint4 per 64-half row
            int cu  = (idx & 7) * 4;        // 4 ull (8 floats) per uint4
            const __half2* hv = (const __half2*)&v;
            #pragma unroll
            for (int k=0;k<4;k++){
                float2 f = __half22float2(hv[k]);
                rows[wid][row*33 + cu + k] = pack2(f.x, f.y);
            }
        }
        __syncwarp();
        const ull* hr  = &rows[wid][l*33];
        const ull* wd2 = (const ull*)wd_f;
        #pragma unroll
        for (int o=0;o<ODIM;o++){
            ull a0=0ULL, a1=0ULL;
            #pragma unroll
            for (int kk=0;kk<32;kk+=2){
                a0 = ffma2(hr[kk],   wd2[o*32+kk],   a0);
                a1 = ffma2(hr[kk+1], wd2[o*32+kk+1], a1);
            }
            float2 s = unpack2(fadd2(a0,a1));
            outsh[wid][l*ODIM + o] = fmaxf(s.x + s.y + bd[o], 0.f);
        }
        __syncwarp();
        // coalesced store: 32*11 = 352 floats = 88 float4
        float4* dst = (float4*)(out + (size_t)g * (32*ODIM));
        const float4* osrc = (const float4*)&outsh[wid][0];
        #pragma unroll
        for (int q=0;q<3;q++){
            int idx = q*32 + l;
            if (idx < 88) dst[idx] = osrc[idx];
        }
        __syncwarp();
    }
}

extern "C" void kernel_launch(void* const* d_in, const int* in_sizes, int n_in,
                              void* d_out, int out_size)
{
    const float* x     = (const float*)d_in[0];
    const float* W_ih  = (const float*)d_in[1];
    const float* b_ih  = (const float*)d_in[2];
    const float* W_hh  = (const float*)d_in[3];
    const float* b_hh  = (const float*)d_in[4];
    const float* W_dec = (const float*)d_in[5];
    const float* b_dec = (const float*)d_in[6];
    float* out = (float*)d_out;

    (void)in_sizes; (void)n_in; (void)out_size;

    pad_x_kernel<<<(BB*TT)/256, 256>>>(x);
    rnn_kernel<<<BB/4, 128>>>(W_ih, b_ih, W_hh, b_hh, out + (size_t)BB*TT*ODIM);
    dec_kernel<<<1024, 128>>>(W_dec, b_dec, out);
}

// round 15
// speedup vs baseline: 1.1205x; 1.0147x over previous
#include <cuda_runtime.h>
#include <cuda_fp16.h>
#include <cstdint>

typedef unsigned long long ull;

#define BB 512
#define TT 1024
#define IDIM 15
#define HH 64
#define ODIM 11
#define CHUNK 64
#define NCHUNK (TT/CHUNK)
// raw x chunk: 64 steps * 15 floats = 960 floats = 3840B = 240 x 16B
#define XCH_FLOATS 960
#define XCH_UNITS  240
// smem row buffer: 4 guard floats front (so odd-row leading pair is in-array),
// 960 data floats, 12 guard floats tail (even-row trailing pair reads 1 past).
#define XBUF_FLOATS 976

// scratch (static __device__ — no allocations in kernel_launch)
__device__ __align__(16) __half2 g_hs[(size_t)BB*TT*32];   // hidden states, fp16 pairs

// ---- f32x2 helpers ----
__device__ __forceinline__ ull ffma2(ull a, ull b, ull c){
    ull d; asm("fma.rn.f32x2 %0, %1, %2, %3;" : "=l"(d) : "l"(a), "l"(b), "l"(c)); return d;
}
__device__ __forceinline__ ull fadd2(ull a, ull b){
    ull d; asm("add.rn.f32x2 %0, %1, %2;" : "=l"(d) : "l"(a), "l"(b)); return d;
}
__device__ __forceinline__ ull pack2(float x, float y){
    ull r; asm("mov.b64 %0, {%1, %2};" : "=l"(r) : "f"(x), "f"(y)); return r;
}
__device__ __forceinline__ float2 unpack2(ull v){
    float2 r; asm("mov.b64 {%0, %1}, %2;" : "=f"(r.x), "=f"(r.y) : "l"(v)); return r;
}

// ---- kernel 1: fused xproj(raw x) + recurrence. warp == one batch row ----
__global__ void __launch_bounds__(128,1) rnn_kernel(
    const float* __restrict__ x,
    const float* __restrict__ W_ih, const float* __restrict__ b_ih,
    const float* __restrict__ W_hh, const float* __restrict__ b_hh,
    float* __restrict__ h_out)
{
    // [buf][warp][4 guard | 960 data | 12 guard]
    __shared__ __align__(16) float xs[2][4][XBUF_FLOATS];
    __shared__ __align__(16) ull  h_sh[4][2][32];        // per-warp double-buffered h

    const int wid = threadIdx.x >> 5;
    const int l   = threadIdx.x & 31;
    const int b   = blockIdx.x * 4 + wid;
    const int j0 = 2*l, j1 = 2*l + 1;

    // W_hh rows j0,j1 in registers, k-paired as f32x2
    ull w0[32], w1[32];
    {
        const ull* wp = (const ull*)W_hh;
        #pragma unroll
        for (int q=0;q<32;q++){ w0[q] = wp[j0*32+q]; w1[q] = wp[j1*32+q]; }
    }
    // W_ih rows with parity-specific pairing:
    // even rows (byte 60*tt): pairs (x0,x1)..(x12,x13),(x14,stray) -> wE[7]=(w14,0)
    // odd rows:               pairs (stray,x0),(x1,x2)..(x13,x14)  -> wO[0]=(0,w0)
    ull wE0[8], wE1[8], wO0[8], wO1[8];
    {
        float r0[IDIM], r1[IDIM];
        #pragma unroll
        for (int i=0;i<IDIM;i++){ r0[i] = W_ih[j0*IDIM+i]; r1[i] = W_ih[j1*IDIM+i]; }
        #pragma unroll
        for (int q=0;q<7;q++){
            wE0[q] = pack2(r0[2*q],   r0[2*q+1]);
            wE1[q] = pack2(r1[2*q],   r1[2*q+1]);
            wO0[q+1] = pack2(r0[2*q+1], r0[2*q+2]);
            wO1[q+1] = pack2(r1[2*q+1], r1[2*q+2]);
        }
        wE0[7] = pack2(r0[14], 0.f);  wE1[7] = pack2(r1[14], 0.f);
        wO0[0] = pack2(0.f, r0[0]);   wO1[0] = pack2(0.f, r1[0]);
    }
    const ull bias0 = pack2(b_ih[j0]+b_hh[j0], 0.f);
    const ull bias1 = pack2(b_ih[j1]+b_hh[j1], 0.f);

    h_sh[wid][1][l] = 0ULL;   // h_{-1} = 0 (t=0 reads slot 1)

    // cp.async target: data region starts at +16B (4 floats)
    const uint32_t xs_base0 = (uint32_t)__cvta_generic_to_shared(&xs[0][wid][4]);
    const float* xsrc = x + (size_t)b * (TT*IDIM);

    auto prefetch = [&](int c){
        if (c < NCHUNK){
            const float* src = xsrc + (size_t)c * XCH_FLOATS;
            uint32_t dst = xs_base0 + (uint32_t)(c & 1) * (uint32_t)sizeof(xs[0]);
            #pragma unroll
            for (int q=0;q<8;q++){
                int idx = q*32 + l;              // 0..255, copy 240 units
                if (idx < XCH_UNITS){
                    asm volatile("cp.async.ca.shared.global [%0], [%1], 16;\n"
                        :: "r"(dst + (uint32_t)(idx*16)), "l"(src + idx*4) : "memory");
                }
            }
        }
        asm volatile("cp.async.commit_group;\n" ::: "memory");
    };

    prefetch(0);

    __half2* hs_ptr = g_hs + (size_t)b * (TT*32) + l;
    ull hlast = 0ULL;

    for (int c=0; c<NCHUNK; c++){
        prefetch(c+1);                                        // overlap next chunk
        asm volatile("cp.async.wait_group 1;\n" ::: "memory");// chunk c landed
        __syncwarp();
        const float* xbuf = &xs[c & 1][wid][0];               // guard at [0..3]

        #pragma unroll 4
        for (int tt=0; tt<CHUNK; tt++){
            const int rs = (tt & 1) ^ 1;   // read  h_{t-1}
            const int ws =  tt & 1;        // write h_t
            // ---- xproj from raw 15-float rows; parity compile-time (unroll 4) ----
            ull ax0 = bias0, ax1 = bias1;
            if ((tt & 1) == 0){
                // row data at float 4 + 15*tt; byte 16+60tt ≡ 0 (mod 8)
                const ull* xv = (const ull*)(xbuf + 4 + 15*tt);
                #pragma unroll
                for (int q=0;q<8;q++){
                    ull xq = xv[q];
                    ax0 = ffma2(xq, wE0[q], ax0);
                    ax1 = ffma2(xq, wE1[q], ax1);
                }
            } else {
                // shifted pairs start at float 3 + 15*tt; byte 12+60tt ≡ 0 (mod 8)
                const ull* xv = (const ull*)(xbuf + 3 + 15*tt);
                #pragma unroll
                for (int q=0;q<8;q++){
                    ull xq = xv[q];
                    ax0 = ffma2(xq, wO0[q], ax0);
                    ax1 = ffma2(xq, wO1[q], ax1);
                }
            }
            // ---- recurrence: chains seeded with xproj accumulators ----
            const ulonglong2* hp = (const ulonglong2*)&h_sh[wid][rs][0];
            ull aa0=ax0, aa1=ax1, ab0=0ULL, ab1=0ULL;
            #pragma unroll
            for (int q=0;q<16;q++){
                ulonglong2 hv = hp[q];
                aa0 = ffma2(hv.x, w0[2*q],   aa0);
                aa1 = ffma2(hv.x, w1[2*q],   aa1);
                ab0 = ffma2(hv.y, w0[2*q+1], ab0);
                ab1 = ffma2(hv.y, w1[2*q+1], ab1);
            }
            float2 s0 = unpack2(fadd2(aa0, ab0));
            float2 s1 = unpack2(fadd2(aa1, ab1));
            float h0v = fmaxf(s0.x + s0.y, 0.f);
            float h1v = fmaxf(s1.x + s1.y, 0.f);
            ull hpk = pack2(h0v, h1v);
            h_sh[wid][ws][l] = hpk;                    // fp32 exchange for next step
            *hs_ptr = __floats2half2_rn(h0v, h1v);     // fp16 pair for decoder (STG.32)
            hs_ptr += 32;
            hlast = hpk;
            asm volatile("" ::: "memory");
        }
    }
    // final hidden state -> tail of d_out ( [1,B,H] ), full fp32
    ((ull*)h_out)[b*32 + l] = hlast;
}

// ---- kernel 2: decoder out = relu(hs @ W_dec^T + b_dec), fp16 hs -> fp32 math ----
__global__ void __launch_bounds__(128) dec_kernel(
    const float* __restrict__ W_dec, const float* __restrict__ b_dec,
    float* __restrict__ out)
{
    __shared__ __align__(16) float wd_f[ODIM*HH];
    __shared__ float bd[ODIM];
    __shared__ __align__(16) ull  rows[4][32*33];       // fp32 pairs, padded stride
    __shared__ __align__(16) float outsh[4][32*ODIM];

    for (int i = threadIdx.x; i < ODIM*HH; i += 128) wd_f[i] = W_dec[i];
    if (threadIdx.x < ODIM) bd[threadIdx.x] = b_dec[threadIdx.x];
    __syncthreads();

    const int wid = threadIdx.x >> 5;
    const int l   = threadIdx.x & 31;
    const int ngroups = (BB*TT)/32;   // 16384 groups of 32 rows

    for (int g = blockIdx.x*4 + wid; g < ngroups; g += gridDim.x*4){
        // coalesced load of 32 rows x 64 halfs (4KB); convert to fp32 while staging
        const uint4* src = (const uint4*)(g_hs + (size_t)g * (32*32));
        #pragma unroll
        for (int q=0;q<8;q++){
            int idx = q*32 + l;             // 0..255 (16B = 8 halfs each)
            uint4 v = src[idx];
            int row = idx >> 3;             // 8 uint4 per 64-half row
            int cu  = (idx & 7) * 4;        // 4 ull (8 floats) per uint4
            const __half2* hv = (const __half2*)&v;
            #pragma unroll
            for (int k=0;k<4;k++){
                float2 f = __half22float2(hv[k]);
                rows[wid][row*33 + cu + k] = pack2(f.x, f.y);
            }
        }
        __syncwarp();
        const ull* hr  = &rows[wid][l*33];
        const ull* wd2 = (const ull*)wd_f;
        #pragma unroll
        for (int o=0;o<ODIM;o++){
            ull a0=0ULL, a1=0ULL;
            #pragma unroll
            for (int kk=0;kk<32;kk+=2){
                a0 = ffma2(hr[kk],   wd2[o*32+kk],   a0);
                a1 = ffma2(hr[kk+1], wd2[o*32+kk+1], a1);
            }
            float2 s = unpack2(fadd2(a0,a1));
            outsh[wid][l*ODIM + o] = fmaxf(s.x + s.y + bd[o], 0.f);
        }
        __syncwarp();
        // coalesced store: 32*11 = 352 floats = 88 float4
        float4* dst = (float4*)(out + (size_t)g * (32*ODIM));
        const float4* osrc = (const float4*)&outsh[wid][0];
        #pragma unroll
        for (int q=0;q<3;q++){
            int idx = q*32 + l;
            if (idx < 88) dst[idx] = osrc[idx];
        }
        __syncwarp();
    }
}

extern "C" void kernel_launch(void* const* d_in, const int* in_sizes, int n_in,
                              void* d_out, int out_size)
{
    const float* x     = (const float*)d_in[0];
    const float* W_ih  = (const float*)d_in[1];
    const float* b_ih  = (const float*)d_in[2];
    const float* W_hh  = (const float*)d_in[3];
    const float* b_hh  = (const float*)d_in[4];
    const float* W_dec = (const float*)d_in[5];
    const float* b_dec = (const float*)d_in[6];
    float* out = (float*)d_out;

    (void)in_sizes; (void)n_in; (void)out_size;

    rnn_kernel<<<BB/4, 128>>>(x, W_ih, b_ih, W_hh, b_hh, out + (size_t)BB*TT*ODIM);
    dec_kernel<<<2048, 128>>>(W_dec, b_dec, out);
}